// round 9
// baseline (speedup 1.0000x reference)
#include <cuda_runtime.h>
#include <math.h>

// Problem constants (fixed by the reference)
#define B_FRAMES 256
#define N_COLS   576
#define MR_ROWS  144
#define Z_LIFT   24
#define N_IT     3
#define ROW_DEG  15
#define N_MSG    (MR_ROWS * ROW_DEG)   // 2160
#define NB_A     ((MR_ROWS / Z_LIFT) * (N_COLS / Z_LIFT) * N_IT)  // 432
#define NCHUNK   (N_COLS / 32)         // 18 column chunks per row
#define NRW      5                     // ceil(144/32) row-mask words per column

#define FPB   2                        // frames per CTA
#define BT    512                      // threads per CTA (256 per frame)
#define GRID  (B_FRAMES / FPB)         // 128 CTAs -> 1 per SM, single wave
#define NPASS (MR_ROWS / 16)           // 9 row passes (16-lane groups)

// Graph structure scratch (rebuilt from H every launch; fully overwritten -> deterministic)
__device__ int g_row_cols[N_MSG];               // CSR: 15 column ids per row (ascending)
__device__ unsigned g_row_mask[MR_ROWS][NCHUNK];// per-row 32-col occupancy bitmask
__device__ int g_row_pref[MR_ROWS][NCHUNK];     // #ones in row before this chunk
__device__ int g_col_ptr[N_COLS + 1];           // CSC ranges
__device__ int g_col_edges[N_MSG];              // CSC edge ids, row-ascending

// ---------------------------------------------------------------------------
// Kernel 1: row extraction. One warp per check row. All 18 chunk loads are
// issued up-front (MLP=18 -> one DRAM latency round), then ballot-compact.
// ---------------------------------------------------------------------------
__global__ void nms_prep_rows(const int* __restrict__ H) {
    int warp = (blockIdx.x * blockDim.x + threadIdx.x) >> 5;
    int lane = threadIdx.x & 31;
    if (warp >= MR_ROWS) return;
    const int* row = H + warp * N_COLS;

    int vals[NCHUNK];
    #pragma unroll
    for (int j = 0; j < NCHUNK; ++j) vals[j] = row[j * 32 + lane];

    int cnt = 0;
    #pragma unroll
    for (int j = 0; j < NCHUNK; ++j) {
        unsigned ball = __ballot_sync(0xffffffffu, vals[j] != 0);
        if (lane == 0) {
            g_row_mask[warp][j] = ball;
            g_row_pref[warp][j] = cnt;
        }
        int before = __popc(ball & ((1u << lane) - 1u));
        if (vals[j] != 0) g_row_cols[warp * ROW_DEG + cnt + before] = j * 32 + lane;
        cnt += __popc(ball);
    }
}

// ---------------------------------------------------------------------------
// Kernel 2: build packed column CSC from the row bitmasks. One CTA, 576
// threads (thread = column). No atomics, no sorting: edges emitted in
// row-ascending order by construction -> deterministic float-sum order.
// ---------------------------------------------------------------------------
__global__ void nms_colbuild() {
    __shared__ unsigned s_mask[MR_ROWS][NCHUNK];   // 10.4 KB
    __shared__ int      s_pref[MR_ROWS][NCHUNK];   // 10.4 KB
    __shared__ int      s_wsum[N_COLS / 32];

    const int tid  = threadIdx.x;          // 0..575
    const int lane = tid & 31;
    const int w    = tid >> 5;

    // Stage row masks/prefixes (coalesced)
    for (int i = tid; i < MR_ROWS * NCHUNK; i += N_COLS) {
        s_mask[0][i] = g_row_mask[0][i];
        s_pref[0][i] = g_row_pref[0][i];
    }
    __syncthreads();

    const int cw  = tid >> 5;              // my column's chunk word
    const int cb  = tid & 31;              // my bit within the chunk
    const unsigned below = (1u << cb) - 1u;

    // Build my column's row-occupancy bitmask (warp-broadcast smem reads)
    unsigned colmask[NRW];
    #pragma unroll
    for (int j = 0; j < NRW; ++j) colmask[j] = 0u;
    #pragma unroll 4
    for (int m = 0; m < MR_ROWS; ++m) {
        unsigned bit = (s_mask[m][cw] >> cb) & 1u;
        colmask[m >> 5] |= bit << (m & 31);
    }
    int cnt = 0;
    #pragma unroll
    for (int j = 0; j < NRW; ++j) cnt += __popc(colmask[j]);

    // Block exclusive scan over 576 counts
    int x = cnt;
    #pragma unroll
    for (int d = 1; d < 32; d <<= 1) {
        int o = __shfl_up_sync(0xffffffffu, x, d);
        if (lane >= d) x += o;
    }
    if (lane == 31) s_wsum[w] = x;
    __syncthreads();
    if (w == 0 && lane < N_COLS / 32) {
        int y = s_wsum[lane], yi = y;
        #pragma unroll
        for (int d = 1; d < 32; d <<= 1) {
            int o = __shfl_up_sync(0x3ffffu, yi, d);
            if (lane >= d) yi += o;
        }
        s_wsum[lane] = yi - y;
    }
    __syncthreads();
    const int excl = x - cnt + s_wsum[w];
    g_col_ptr[tid] = excl;
    if (tid == N_COLS - 1) g_col_ptr[N_COLS] = excl + cnt;

    // Emit edge ids in ascending row order
    int pos = excl;
    #pragma unroll
    for (int j = 0; j < NRW; ++j) {
        unsigned word = colmask[j];
        while (word) {
            int m = j * 32 + (__ffs(word) - 1);
            word &= word - 1;
            unsigned rm = s_mask[m][cw];
            int slot = s_pref[m][cw] + __popc(rm & below);
            g_col_edges[pos++] = m * ROW_DEG + slot;
        }
    }
}

// ---------------------------------------------------------------------------
// Kernel 3: decoder. 2 frames/CTA, 16 lanes per check row, NO atomics.
// Per-edge state in registers; column sums via packed CSC gather in smem.
// ---------------------------------------------------------------------------
__global__ __launch_bounds__(BT) void nms_decode(
    const float* __restrict__ r,
    const float* __restrict__ alpha,
    const float* __restrict__ beta,
    float* __restrict__ out)
{
    __shared__ float s_r[FPB][N_COLS];
    __shared__ float s_sumE[FPB][N_COLS];
    __shared__ float s_E[FPB][N_MSG];
    __shared__ float s_a[NB_A];
    __shared__ float s_b[NB_A];
    __shared__ int   s_cp[N_COLS + 1];
    __shared__ int   s_ce[N_MSG];

    const int tid    = threadIdx.x;
    const int f      = tid >> 8;           // frame within CTA
    const int ft     = tid & 255;          // thread id within frame
    const int grp    = ft >> 4;            // 16-lane row group (0..15)
    const int k      = ft & 15;            // edge slot (15 = padding)
    const int b      = blockIdx.x * FPB + f;
    const int lane32 = tid & 31;
    const bool act   = (k < ROW_DEG);
    const unsigned hmask = 0xFFFFu << (lane32 & 16);

    // Stage shared inputs
    for (int i = tid; i < NB_A; i += BT) { s_a[i] = alpha[i]; s_b[i] = beta[i]; }
    for (int i = tid; i <= N_COLS; i += BT) s_cp[i] = g_col_ptr[i];
    for (int i = tid; i < N_MSG; i += BT) s_ce[i] = g_col_edges[i];
    for (int i = ft; i < N_COLS; i += 256) {
        s_r[f][i] = r[b * N_COLS + i];
        s_sumE[f][i] = 0.0f;
    }

    // Per-edge register state (9 edges per thread)
    int   rc[NPASS];
    int   aoff[NPASS];
    float rv[NPASS];
    float Ep[NPASS];
    #pragma unroll
    for (int p = 0; p < NPASS; ++p) {
        int row = p * 16 + grp;
        int e = row * ROW_DEG + (act ? k : 0);
        rc[p]   = act ? g_row_cols[e] : 0;
        aoff[p] = (row / Z_LIFT) * ((N_COLS / Z_LIFT) * N_IT)
                + (rc[p] / Z_LIFT) * N_IT;
        Ep[p]   = 0.0f;
    }
    __syncthreads();
    #pragma unroll
    for (int p = 0; p < NPASS; ++p) rv[p] = s_r[f][rc[p]];

    for (int it = 0; it < N_IT; ++it) {
        // ---- check-node phase (edge-parallel, writes s_E) ----
        #pragma unroll
        for (int p = 0; p < NPASS; ++p) {
            float v = rv[p] + s_sumE[f][rc[p]] - Ep[p];   // v->c message
            float av = act ? fabsf(v) : INFINITY;
            unsigned avb = __float_as_uint(av);           // order-preserving (av>=0)

            unsigned negb = __ballot_sync(0xffffffffu, act && (v < 0.0f));

            unsigned m1 = __reduce_min_sync(hmask, avb);
            unsigned bm = __ballot_sync(0xffffffffu, avb == m1) & hmask;
            const bool leader = (lane32 == (__ffs(bm) - 1));  // first argmin
            unsigned m2 = __reduce_min_sync(hmask, leader ? 0x7f800000u : avb);

            if (act) {
                float sel = __uint_as_float(leader ? m2 : m1);
                int   ai  = aoff[p] + it;
                float mag = fmaxf(sel - s_b[ai], 0.0f);
                int parity = __popc(negb & hmask) & 1;
                int neg = parity ^ ((v < 0.0f) ? 1 : 0);
                float E = s_a[ai] * mag;
                E = neg ? -E : E;
                E = (m1 == 0u) ? 0.0f : E;                // any zero in row -> E = 0
                Ep[p] = E;
                s_E[f][(p * 16 + grp) * ROW_DEG + k] = E;
            }
        }
        __syncthreads();

        // ---- column-sum phase: CSC gather from smem (no atomics) ----
        for (int i = tid; i < FPB * N_COLS; i += BT) {
            int f2 = i / N_COLS;
            int c  = i - f2 * N_COLS;
            int beg = s_cp[c], end = s_cp[c + 1];
            float s = 0.0f;
            for (int j = beg; j < end; ++j) s += s_E[f2][s_ce[j]];
            s_sumE[f2][c] = s;
        }
        __syncthreads();
    }

    // Posterior LLRs
    for (int i = ft; i < N_COLS; i += 256)
        out[b * N_COLS + i] = s_r[f][i] + s_sumE[f][i];
}

extern "C" void kernel_launch(void* const* d_in, const int* in_sizes, int n_in,
                              void* d_out, int out_size) {
    const float* r     = (const float*)d_in[0];   // (256, 576)
    const float* alpha = (const float*)d_in[1];   // (6, 24, 3)
    const float* beta  = (const float*)d_in[2];   // (6, 24, 3)
    const int*   H     = (const int*)d_in[3];     // (144, 576)
    float* out = (float*)d_out;                   // (256, 576)

    nms_prep_rows<<<18, 256>>>(H);
    nms_colbuild<<<1, N_COLS>>>();
    nms_decode<<<GRID, BT>>>(r, alpha, beta, out);
}

// round 10
// speedup vs baseline: 1.0645x; 1.0645x over previous
#include <cuda_runtime.h>
#include <math.h>

// Problem constants (fixed by the reference)
#define B_FRAMES 256
#define N_COLS   576
#define MR_ROWS  144
#define Z_LIFT   24
#define N_IT     3
#define ROW_DEG  15
#define N_MSG    (MR_ROWS * ROW_DEG)   // 2160
#define NB_A     ((MR_ROWS / Z_LIFT) * (N_COLS / Z_LIFT) * N_IT)  // 432
#define NCHUNK   (N_COLS / 32)         // 18 column chunks per row
#define NRW      5                     // ceil(144/32) row-mask words per column

#define FPB   2                        // frames per CTA
#define BT    512                      // threads per CTA (256 per frame)
#define GRID  (B_FRAMES / FPB)         // 128 CTAs -> 1 per SM, single wave
#define NPASS (MR_ROWS / 16)           // 9 row passes (16-lane groups)

// Graph structure scratch (rebuilt from H every launch; fully overwritten -> deterministic)
__device__ int g_row_cols[N_MSG];               // CSR: 15 column ids per row (ascending)
__device__ unsigned g_row_mask[MR_ROWS][NCHUNK];// per-row 32-col occupancy bitmask
__device__ int g_row_pref[MR_ROWS][NCHUNK];     // #ones in row before this chunk
__device__ int g_col_ptr[N_COLS + 1];           // CSC ranges
__device__ int g_col_edges[N_MSG];              // CSC edge ids, row-ascending

// ---------------------------------------------------------------------------
// Kernel 1: row extraction. One warp per check row. All 18 chunk loads are
// issued up-front (MLP=18 -> one DRAM latency round), then ballot-compact.
// ---------------------------------------------------------------------------
__global__ void nms_prep_rows(const int* __restrict__ H) {
    int warp = (blockIdx.x * blockDim.x + threadIdx.x) >> 5;
    int lane = threadIdx.x & 31;
    if (warp >= MR_ROWS) return;
    const int* row = H + warp * N_COLS;

    int vals[NCHUNK];
    #pragma unroll
    for (int j = 0; j < NCHUNK; ++j) vals[j] = row[j * 32 + lane];

    int cnt = 0;
    #pragma unroll
    for (int j = 0; j < NCHUNK; ++j) {
        unsigned ball = __ballot_sync(0xffffffffu, vals[j] != 0);
        if (lane == 0) {
            g_row_mask[warp][j] = ball;
            g_row_pref[warp][j] = cnt;
        }
        int before = __popc(ball & ((1u << lane) - 1u));
        if (vals[j] != 0) g_row_cols[warp * ROW_DEG + cnt + before] = j * 32 + lane;
        cnt += __popc(ball);
    }
}

// ---------------------------------------------------------------------------
// Kernel 2: build packed column CSC from the row bitmasks. One CTA, 576
// threads (thread = column). No atomics, no sorting; edges emitted in
// row-ascending order by construction -> deterministic float-sum order.
// NOTE: the colmask build is fully unrolled with static indices so the
// array lives in REGISTERS (the R6 partial-unroll version spilled to local
// memory -> ~13us of serialized LDL/STL on one SM).
// ---------------------------------------------------------------------------
__global__ void nms_colbuild() {
    __shared__ unsigned s_mask[MR_ROWS][NCHUNK];   // 10.4 KB
    __shared__ int      s_pref[MR_ROWS][NCHUNK];   // 10.4 KB
    __shared__ int      s_wsum[N_COLS / 32];

    const int tid  = threadIdx.x;          // 0..575
    const int lane = tid & 31;
    const int w    = tid >> 5;

    // Stage row masks/prefixes (coalesced)
    for (int i = tid; i < MR_ROWS * NCHUNK; i += N_COLS) {
        s_mask[0][i] = g_row_mask[0][i];
        s_pref[0][i] = g_row_pref[0][i];
    }
    __syncthreads();

    const int cw  = tid >> 5;              // my column's chunk word
    const int cb  = tid & 31;              // my bit within the chunk
    const unsigned below = (1u << cb) - 1u;

    // Build my column's row-occupancy bitmask: all indices static -> registers
    unsigned colmask[NRW];
    #pragma unroll
    for (int j = 0; j < NRW; ++j) {
        unsigned wmask = 0u;
        #pragma unroll
        for (int mm = 0; mm < 32; ++mm) {
            const int m = j * 32 + mm;
            if (m < MR_ROWS) {
                unsigned bit = (s_mask[m][cw] >> cb) & 1u;
                wmask |= bit << mm;
            }
        }
        colmask[j] = wmask;
    }
    int cnt = 0;
    #pragma unroll
    for (int j = 0; j < NRW; ++j) cnt += __popc(colmask[j]);

    // Block exclusive scan over 576 counts
    int x = cnt;
    #pragma unroll
    for (int d = 1; d < 32; d <<= 1) {
        int o = __shfl_up_sync(0xffffffffu, x, d);
        if (lane >= d) x += o;
    }
    if (lane == 31) s_wsum[w] = x;
    __syncthreads();
    if (w == 0 && lane < N_COLS / 32) {
        int y = s_wsum[lane], yi = y;
        #pragma unroll
        for (int d = 1; d < 32; d <<= 1) {
            int o = __shfl_up_sync(0x3ffffu, yi, d);
            if (lane >= d) yi += o;
        }
        s_wsum[lane] = yi - y;
    }
    __syncthreads();
    const int excl = x - cnt + s_wsum[w];
    g_col_ptr[tid] = excl;
    if (tid == N_COLS - 1) g_col_ptr[N_COLS] = excl + cnt;

    // Emit edge ids in ascending row order (j static via unroll; word scalar)
    int pos = excl;
    #pragma unroll
    for (int j = 0; j < NRW; ++j) {
        unsigned word = colmask[j];
        while (word) {
            int m = j * 32 + (__ffs(word) - 1);
            word &= word - 1;
            unsigned rm = s_mask[m][cw];
            int slot = s_pref[m][cw] + __popc(rm & below);
            g_col_edges[pos++] = m * ROW_DEG + slot;
        }
    }
}

// ---------------------------------------------------------------------------
// Kernel 3: decoder. 2 frames/CTA, 16 lanes per check row, NO atomics.
// Per-edge state in registers; column sums via packed CSC gather in smem.
// ---------------------------------------------------------------------------
__global__ __launch_bounds__(BT) void nms_decode(
    const float* __restrict__ r,
    const float* __restrict__ alpha,
    const float* __restrict__ beta,
    float* __restrict__ out)
{
    __shared__ float s_r[FPB][N_COLS];
    __shared__ float s_sumE[FPB][N_COLS];
    __shared__ float s_E[FPB][N_MSG];
    __shared__ float s_a[NB_A];
    __shared__ float s_b[NB_A];
    __shared__ int   s_cp[N_COLS + 1];
    __shared__ int   s_ce[N_MSG];

    const int tid    = threadIdx.x;
    const int f      = tid >> 8;           // frame within CTA
    const int ft     = tid & 255;          // thread id within frame
    const int grp    = ft >> 4;            // 16-lane row group (0..15)
    const int k      = ft & 15;            // edge slot (15 = padding)
    const int b      = blockIdx.x * FPB + f;
    const int lane32 = tid & 31;
    const bool act   = (k < ROW_DEG);
    const unsigned hmask = 0xFFFFu << (lane32 & 16);

    // Stage shared inputs
    for (int i = tid; i < NB_A; i += BT) { s_a[i] = alpha[i]; s_b[i] = beta[i]; }
    for (int i = tid; i <= N_COLS; i += BT) s_cp[i] = g_col_ptr[i];
    for (int i = tid; i < N_MSG; i += BT) s_ce[i] = g_col_edges[i];
    for (int i = ft; i < N_COLS; i += 256) {
        s_r[f][i] = r[b * N_COLS + i];
        s_sumE[f][i] = 0.0f;
    }

    // Per-edge register state (9 edges per thread)
    int   rc[NPASS];
    int   aoff[NPASS];
    float rv[NPASS];
    float Ep[NPASS];
    #pragma unroll
    for (int p = 0; p < NPASS; ++p) {
        int row = p * 16 + grp;
        int e = row * ROW_DEG + (act ? k : 0);
        rc[p]   = act ? g_row_cols[e] : 0;
        aoff[p] = (row / Z_LIFT) * ((N_COLS / Z_LIFT) * N_IT)
                + (rc[p] / Z_LIFT) * N_IT;
        Ep[p]   = 0.0f;
    }
    __syncthreads();
    #pragma unroll
    for (int p = 0; p < NPASS; ++p) rv[p] = s_r[f][rc[p]];

    for (int it = 0; it < N_IT; ++it) {
        // ---- check-node phase (edge-parallel, writes s_E) ----
        #pragma unroll
        for (int p = 0; p < NPASS; ++p) {
            float v = rv[p] + s_sumE[f][rc[p]] - Ep[p];   // v->c message
            float av = act ? fabsf(v) : INFINITY;
            unsigned avb = __float_as_uint(av);           // order-preserving (av>=0)

            unsigned negb = __ballot_sync(0xffffffffu, act && (v < 0.0f));

            unsigned m1 = __reduce_min_sync(hmask, avb);
            unsigned bm = __ballot_sync(0xffffffffu, avb == m1) & hmask;
            const bool leader = (lane32 == (__ffs(bm) - 1));  // first argmin
            unsigned m2 = __reduce_min_sync(hmask, leader ? 0x7f800000u : avb);

            if (act) {
                float sel = __uint_as_float(leader ? m2 : m1);
                int   ai  = aoff[p] + it;
                float mag = fmaxf(sel - s_b[ai], 0.0f);
                int parity = __popc(negb & hmask) & 1;
                int neg = parity ^ ((v < 0.0f) ? 1 : 0);
                float E = s_a[ai] * mag;
                E = neg ? -E : E;
                E = (m1 == 0u) ? 0.0f : E;                // any zero in row -> E = 0
                Ep[p] = E;
                s_E[f][(p * 16 + grp) * ROW_DEG + k] = E;
            }
        }
        __syncthreads();

        // ---- column-sum phase: CSC gather from smem (no atomics) ----
        for (int i = tid; i < FPB * N_COLS; i += BT) {
            int f2 = i / N_COLS;
            int c  = i - f2 * N_COLS;
            int beg = s_cp[c], end = s_cp[c + 1];
            float s = 0.0f;
            for (int j = beg; j < end; ++j) s += s_E[f2][s_ce[j]];
            s_sumE[f2][c] = s;
        }
        __syncthreads();
    }

    // Posterior LLRs
    for (int i = ft; i < N_COLS; i += 256)
        out[b * N_COLS + i] = s_r[f][i] + s_sumE[f][i];
}

extern "C" void kernel_launch(void* const* d_in, const int* in_sizes, int n_in,
                              void* d_out, int out_size) {
    const float* r     = (const float*)d_in[0];   // (256, 576)
    const float* alpha = (const float*)d_in[1];   // (6, 24, 3)
    const float* beta  = (const float*)d_in[2];   // (6, 24, 3)
    const int*   H     = (const int*)d_in[3];     // (144, 576)
    float* out = (float*)d_out;                   // (256, 576)

    nms_prep_rows<<<18, 256>>>(H);
    nms_colbuild<<<1, N_COLS>>>();
    nms_decode<<<GRID, BT>>>(r, alpha, beta, out);
}

// round 11
// speedup vs baseline: 1.2138x; 1.1402x over previous
#include <cuda_runtime.h>
#include <math.h>

// Problem constants (fixed by the reference)
#define B_FRAMES 256
#define N_COLS   576
#define MR_ROWS  144
#define Z_LIFT   24
#define N_IT     3
#define ROW_DEG  15
#define N_MSG    (MR_ROWS * ROW_DEG)   // 2160
#define NB_A     ((MR_ROWS / Z_LIFT) * (N_COLS / Z_LIFT) * N_IT)  // 432
#define NCHUNK   (N_COLS / 32)         // 18 column chunks per row
#define NRW      5                     // ceil(144/32) row-mask words per column

#define FPB   2                        // frames per CTA
#define BT    512                      // threads per CTA (256 per frame)
#define GRID  (B_FRAMES / FPB)         // 128 CTAs -> 1 per SM, single wave
#define NPASS (MR_ROWS / 16)           // 9 row passes (16-lane groups)

// Graph structure scratch (rebuilt from H every launch; fully overwritten -> deterministic)
__device__ int g_row_cols[N_MSG];               // CSR: 15 column ids per row (ascending)
__device__ unsigned g_row_mask[MR_ROWS][NCHUNK];// per-row 32-col occupancy bitmask
__device__ int g_row_pref[MR_ROWS][NCHUNK];     // #ones in row before this chunk
__device__ int g_col_ptr[N_COLS + 1];           // CSC ranges
__device__ int g_col_edges[N_MSG];              // CSC edge ids, row-ascending

// ---------------------------------------------------------------------------
// Kernel 1: row extraction. One warp per check row. All 18 chunk loads are
// issued up-front (MLP=18 -> one DRAM latency round), then ballot-compact.
// ---------------------------------------------------------------------------
__global__ void nms_prep_rows(const int* __restrict__ H) {
    int warp = (blockIdx.x * blockDim.x + threadIdx.x) >> 5;
    int lane = threadIdx.x & 31;
    if (warp >= MR_ROWS) return;
    const int* row = H + warp * N_COLS;

    int vals[NCHUNK];
    #pragma unroll
    for (int j = 0; j < NCHUNK; ++j) vals[j] = row[j * 32 + lane];

    int cnt = 0;
    #pragma unroll
    for (int j = 0; j < NCHUNK; ++j) {
        unsigned ball = __ballot_sync(0xffffffffu, vals[j] != 0);
        if (lane == 0) {
            g_row_mask[warp][j] = ball;
            g_row_pref[warp][j] = cnt;
        }
        int before = __popc(ball & ((1u << lane) - 1u));
        if (vals[j] != 0) g_row_cols[warp * ROW_DEG + cnt + before] = j * 32 + lane;
        cnt += __popc(ball);
    }
}

// ---------------------------------------------------------------------------
// Kernel 2: build packed column CSC from the row bitmasks. One CTA, 576
// threads (thread = column). No atomics, no sorting; edges emitted in
// row-ascending order by construction -> deterministic float-sum order.
// colmask build fully unrolled with static indices (register-resident).
// ---------------------------------------------------------------------------
__global__ void nms_colbuild() {
    __shared__ unsigned s_mask[MR_ROWS][NCHUNK];   // 10.4 KB
    __shared__ int      s_pref[MR_ROWS][NCHUNK];   // 10.4 KB
    __shared__ int      s_wsum[N_COLS / 32];

    const int tid  = threadIdx.x;          // 0..575
    const int lane = tid & 31;
    const int w    = tid >> 5;

    for (int i = tid; i < MR_ROWS * NCHUNK; i += N_COLS) {
        s_mask[0][i] = g_row_mask[0][i];
        s_pref[0][i] = g_row_pref[0][i];
    }
    __syncthreads();

    const int cw  = tid >> 5;              // my column's chunk word
    const int cb  = tid & 31;              // my bit within the chunk
    const unsigned below = (1u << cb) - 1u;

    unsigned colmask[NRW];
    #pragma unroll
    for (int j = 0; j < NRW; ++j) {
        unsigned wmask = 0u;
        #pragma unroll
        for (int mm = 0; mm < 32; ++mm) {
            const int m = j * 32 + mm;
            if (m < MR_ROWS) {
                unsigned bit = (s_mask[m][cw] >> cb) & 1u;
                wmask |= bit << mm;
            }
        }
        colmask[j] = wmask;
    }
    int cnt = 0;
    #pragma unroll
    for (int j = 0; j < NRW; ++j) cnt += __popc(colmask[j]);

    // Block exclusive scan over 576 counts
    int x = cnt;
    #pragma unroll
    for (int d = 1; d < 32; d <<= 1) {
        int o = __shfl_up_sync(0xffffffffu, x, d);
        if (lane >= d) x += o;
    }
    if (lane == 31) s_wsum[w] = x;
    __syncthreads();
    if (w == 0 && lane < N_COLS / 32) {
        int y = s_wsum[lane], yi = y;
        #pragma unroll
        for (int d = 1; d < 32; d <<= 1) {
            int o = __shfl_up_sync(0x3ffffu, yi, d);
            if (lane >= d) yi += o;
        }
        s_wsum[lane] = yi - y;
    }
    __syncthreads();
    const int excl = x - cnt + s_wsum[w];
    g_col_ptr[tid] = excl;
    if (tid == N_COLS - 1) g_col_ptr[N_COLS] = excl + cnt;

    int pos = excl;
    #pragma unroll
    for (int j = 0; j < NRW; ++j) {
        unsigned word = colmask[j];
        while (word) {
            int m = j * 32 + (__ffs(word) - 1);
            word &= word - 1;
            unsigned rm = s_mask[m][cw];
            int slot = s_pref[m][cw] + __popc(rm & below);
            g_col_edges[pos++] = m * ROW_DEG + slot;
        }
    }
}

// ---------------------------------------------------------------------------
// Kernel 3: decoder. 2 frames/CTA, 16 lanes per check row, NO atomics, NO
// divergent-mask reduce intrinsics (the R6 __reduce_min_sync with a per-half
// mask compiled to a serial software fallback and cost ~13us). Row reduction
// is a uniform width-16 shfl_xor butterfly carrying (min1, min2, argmin).
// ---------------------------------------------------------------------------
__global__ __launch_bounds__(BT) void nms_decode(
    const float* __restrict__ r,
    const float* __restrict__ alpha,
    const float* __restrict__ beta,
    float* __restrict__ out)
{
    __shared__ float s_r[FPB][N_COLS];
    __shared__ float s_sumE[FPB][N_COLS];
    __shared__ float s_E[FPB][N_MSG];
    __shared__ float s_a[NB_A];
    __shared__ float s_b[NB_A];
    __shared__ int   s_cp[N_COLS + 1];
    __shared__ int   s_ce[N_MSG];

    const int tid    = threadIdx.x;
    const int f      = tid >> 8;           // frame within CTA
    const int ft     = tid & 255;          // thread id within frame
    const int grp    = ft >> 4;            // 16-lane row group (0..15)
    const int k      = ft & 15;            // edge slot (15 = padding)
    const int b      = blockIdx.x * FPB + f;
    const int lane32 = tid & 31;
    const bool act   = (k < ROW_DEG);
    const unsigned hmask = 0xFFFFu << (lane32 & 16);

    // Stage shared inputs
    for (int i = tid; i < NB_A; i += BT) { s_a[i] = alpha[i]; s_b[i] = beta[i]; }
    for (int i = tid; i <= N_COLS; i += BT) s_cp[i] = g_col_ptr[i];
    for (int i = tid; i < N_MSG; i += BT) s_ce[i] = g_col_edges[i];
    for (int i = ft; i < N_COLS; i += 256) {
        s_r[f][i] = r[b * N_COLS + i];
        s_sumE[f][i] = 0.0f;
    }

    // Per-edge register state (9 edges per thread)
    int   rc[NPASS];
    int   aoff[NPASS];
    float rv[NPASS];
    float Ep[NPASS];
    #pragma unroll
    for (int p = 0; p < NPASS; ++p) {
        int row = p * 16 + grp;
        int e = row * ROW_DEG + (act ? k : 0);
        rc[p]   = act ? g_row_cols[e] : 0;
        aoff[p] = (row / Z_LIFT) * ((N_COLS / Z_LIFT) * N_IT)
                + (rc[p] / Z_LIFT) * N_IT;
        Ep[p]   = 0.0f;
    }
    __syncthreads();
    #pragma unroll
    for (int p = 0; p < NPASS; ++p) rv[p] = s_r[f][rc[p]];

    for (int it = 0; it < N_IT; ++it) {
        // ---- check-node phase (edge-parallel, writes s_E) ----
        #pragma unroll
        for (int p = 0; p < NPASS; ++p) {
            float v = rv[p] + s_sumE[f][rc[p]] - Ep[p];   // v->c message
            float av = act ? fabsf(v) : INFINITY;

            // sign parity of the 16-lane row group (one ballot, both halves)
            unsigned negb = __ballot_sync(0xffffffffu, act && (v < 0.0f));
            int parity = __popc(negb & hmask) & 1;

            // min1/min2/argmin butterfly over the 16-lane group (uniform code)
            float m1 = av, m2 = INFINITY;
            int   k1 = k;
            #pragma unroll
            for (int d = 1; d < 16; d <<= 1) {
                float om1 = __shfl_xor_sync(0xffffffffu, m1, d, 16);
                float om2 = __shfl_xor_sync(0xffffffffu, m2, d, 16);
                int   ok1 = __shfl_xor_sync(0xffffffffu, k1, d, 16);
                if (om1 < m1) { m2 = fminf(m1, om2); m1 = om1; k1 = ok1; }
                else          { m2 = fminf(m2, om1); }
            }

            if (act) {
                float sel = (k == k1) ? m2 : m1;          // exclude self at argmin
                int   ai  = aoff[p] + it;
                float mag = fmaxf(sel - s_b[ai], 0.0f);
                int neg = parity ^ ((v < 0.0f) ? 1 : 0);
                float E = s_a[ai] * mag;
                E = neg ? -E : E;
                E = (m1 == 0.0f) ? 0.0f : E;              // any zero in row -> E = 0
                Ep[p] = E;
                s_E[f][(p * 16 + grp) * ROW_DEG + k] = E;
            }
        }
        __syncthreads();

        // ---- column-sum phase: CSC gather from smem (no atomics, no div) ----
        for (int c = ft; c < N_COLS; c += 256) {
            int beg = s_cp[c], end = s_cp[c + 1];
            float s = 0.0f;
            for (int j = beg; j < end; ++j) s += s_E[f][s_ce[j]];
            s_sumE[f][c] = s;
        }
        __syncthreads();
    }

    // Posterior LLRs
    for (int i = ft; i < N_COLS; i += 256)
        out[b * N_COLS + i] = s_r[f][i] + s_sumE[f][i];
}

extern "C" void kernel_launch(void* const* d_in, const int* in_sizes, int n_in,
                              void* d_out, int out_size) {
    const float* r     = (const float*)d_in[0];   // (256, 576)
    const float* alpha = (const float*)d_in[1];   // (6, 24, 3)
    const float* beta  = (const float*)d_in[2];   // (6, 24, 3)
    const int*   H     = (const int*)d_in[3];     // (144, 576)
    float* out = (float*)d_out;                   // (256, 576)

    nms_prep_rows<<<18, 256>>>(H);
    nms_colbuild<<<1, N_COLS>>>();
    nms_decode<<<GRID, BT>>>(r, alpha, beta, out);
}